// round 2
// baseline (speedup 1.0000x reference)
#include <cuda_runtime.h>
#include <math.h>

#define B_   4
#define S_   2048
#define DIN  512
#define DH   512
#define H_   8
#define HD   64
#define M_   (B_*S_)          // 8192 rows

// -------- scratch (device globals; no allocations allowed) --------
__device__ float g_q [B_*H_*S_*HD];   // [B,H,S,HD]
__device__ float g_k [B_*H_*S_*HD];
__device__ float g_v [B_*H_*S_*HD];
__device__ float g_ao[M_*DH];         // attention output, [B,S,DH]
__device__ float g_o [M_*DH];         // after Wo, pre-LN

// ============================================================================
// GEMM: C[M,512] = X[M,512] @ W[512,512] (+bias) (+pos_enc if pe!=null)
// BM=BN=64, BK=32, 256 threads, 4x4 micro-tile.
// scatter=1: write to [B,H,S,HD] layout (head-split); scatter=0: row-major.
// ============================================================================
__global__ __launch_bounds__(256) void gemm64(
    const float* __restrict__ X, const float* __restrict__ W,
    const float* __restrict__ bias, const float* __restrict__ pe,
    float* __restrict__ out, int scatter)
{
    __shared__ float As[32][65];   // transposed A tile, padded
    __shared__ float Bs[32][64];
    const int tid = threadIdx.x;
    const int tx = tid & 15, ty = tid >> 4;
    const int rowBase = blockIdx.y * 64;
    const int colBase = blockIdx.x * 64;

    float acc[4][4] = {};
    for (int k0 = 0; k0 < 512; k0 += 32) {
        #pragma unroll
        for (int i = 0; i < 2; i++) {
            int r = (tid >> 3) + i * 32;
            int c = (tid & 7) * 4;
            float4 a = *(const float4*)&X[(size_t)(rowBase + r) * 512 + k0 + c];
            As[c  ][r] = a.x; As[c+1][r] = a.y; As[c+2][r] = a.z; As[c+3][r] = a.w;
        }
        #pragma unroll
        for (int i = 0; i < 2; i++) {
            int r = (tid >> 4) + i * 16;
            int c = (tid & 15) * 4;
            *(float4*)&Bs[r][c] = *(const float4*)&W[(size_t)(k0 + r) * 512 + colBase + c];
        }
        __syncthreads();
        #pragma unroll
        for (int kk = 0; kk < 32; kk++) {
            float a[4], b[4];
            #pragma unroll
            for (int i = 0; i < 4; i++) a[i] = As[kk][ty*4 + i];
            float4 b4 = *(float4*)&Bs[kk][tx*4];
            b[0] = b4.x; b[1] = b4.y; b[2] = b4.z; b[3] = b4.w;
            #pragma unroll
            for (int i = 0; i < 4; i++)
                #pragma unroll
                for (int j = 0; j < 4; j++)
                    acc[i][j] += a[i] * b[j];
        }
        __syncthreads();
    }

    #pragma unroll
    for (int i = 0; i < 4; i++) {
        int r = rowBase + ty*4 + i;
        int bb = r >> 11;          // /S_
        int s  = r & 2047;
        #pragma unroll
        for (int j = 0; j < 4; j++) {
            int c = colBase + tx*4 + j;
            float v = acc[i][j] + bias[c];
            if (scatter) {
                if (pe) v += pe[(size_t)s * DH + c];
                int h = c >> 6, d = c & 63;
                out[(((size_t)bb * H_ + h) * S_ + s) * HD + d] = v;
            } else {
                out[(size_t)r * 512 + c] = v;
            }
        }
    }
}

// ============================================================================
// Attention: per block, one (b,h) and TQ=16 query rows. Full-row scores in
// smem -> masked softmax -> attn write -> PV -> g_ao.
// smem: sQ[16][64] + sKT[64][132] (reused as sV[128][64]) + sS[16][2048]
// ============================================================================
#define TQ 16
#define TK 128
#define KTS 132   // padded stride for transposed K tile

__global__ __launch_bounds__(256) void attn_kernel(
    const int* __restrict__ mask, float* __restrict__ attn_out, int write_attn)
{
    extern __shared__ float smem[];
    float* sQ  = smem;               // 1024 floats
    float* sKT = smem + TQ * HD;     // 64*132 = 8448 floats (sV aliases this)
    float* sS  = sKT + 64 * KTS;     // 16*2048 = 32768 floats

    const int qt = blockIdx.x, h = blockIdx.y, b = blockIdx.z;
    const int tid = threadIdx.x;
    const size_t bh = (size_t)(b * H_ + h);
    const float* qbase = g_q + (bh * S_ + (size_t)qt * TQ) * HD;
    const float* kbase = g_k + bh * S_ * HD;
    const float* vbase = g_v + bh * S_ * HD;

    for (int i = tid; i < TQ * HD; i += 256) sQ[i] = qbase[i];

    const int row = tid >> 4;          // 0..15 query row in tile
    const int cb  = (tid & 15) * 8;    // 8 key cols per thread

    // ---------- scores = Q K^T * 1/8 ----------
    for (int kt = 0; kt < S_; kt += TK) {
        __syncthreads();
        #pragma unroll
        for (int it = 0; it < 8; it++) {
            int idx = tid + it * 256;        // 0..2047
            int c   = idx >> 4;              // key row 0..127
            int d4  = (idx & 15) * 4;
            float4 kv = *(const float4*)&kbase[(size_t)(kt + c) * HD + d4];
            sKT[(d4  ) * KTS + c] = kv.x;
            sKT[(d4+1) * KTS + c] = kv.y;
            sKT[(d4+2) * KTS + c] = kv.z;
            sKT[(d4+3) * KTS + c] = kv.w;
        }
        __syncthreads();
        float acc[8] = {};
        #pragma unroll
        for (int d = 0; d < HD; d++) {
            float qv = sQ[row * HD + d];
            const float* kp = &sKT[d * KTS + cb];
            #pragma unroll
            for (int j = 0; j < 8; j++) acc[j] += qv * kp[j];
        }
        #pragma unroll
        for (int j = 0; j < 8; j++)
            sS[row * S_ + kt + cb + j] = acc[j] * 0.125f;
    }
    __syncthreads();

    // ---------- masked softmax (warp w -> rows 2w, 2w+1) ----------
    const int wid = tid >> 5, lane = tid & 31;
    for (int rr = 0; rr < 2; rr++) {
        int r = wid * 2 + rr;
        int qrow = qt * TQ + r;
        const int* mrow = mask + ((size_t)b * S_ + qrow) * S_;
        float* srow = sS + r * S_;
        float mx = -INFINITY;
        for (int j = lane; j < S_; j += 32) {
            float v = mrow[j] ? srow[j] : -INFINITY;
            srow[j] = v;
            mx = fmaxf(mx, v);
        }
        #pragma unroll
        for (int o = 16; o > 0; o >>= 1) mx = fmaxf(mx, __shfl_xor_sync(~0u, mx, o));
        float sum = 0.f;
        for (int j = lane; j < S_; j += 32) {
            float e = __expf(srow[j] - mx);
            srow[j] = e;
            sum += e;
        }
        #pragma unroll
        for (int o = 16; o > 0; o >>= 1) sum += __shfl_xor_sync(~0u, sum, o);
        float inv = 1.f / sum;
        float* arow = attn_out + (bh * S_ + qrow) * S_;
        for (int j = lane; j < S_; j += 32) {
            float p = srow[j] * inv;
            srow[j] = p;
            if (write_attn) arow[j] = p;
        }
    }

    // ---------- PV: out[16,64] = P[16,2048] @ V[2048,64] ----------
    const int qi = tid >> 4;
    const int d4 = (tid & 15) * 4;
    float4 oacc = {0.f, 0.f, 0.f, 0.f};
    float* sV = sKT;                   // reuse, natural layout [128][64]
    for (int vt = 0; vt < S_; vt += TK) {
        __syncthreads();
        const float4* vb4 = (const float4*)&vbase[(size_t)vt * HD];
        for (int i = tid; i < TK * HD / 4; i += 256)
            ((float4*)sV)[i] = vb4[i];
        __syncthreads();
        const float* prow = &sS[qi * S_ + vt];
        #pragma unroll 4
        for (int j = 0; j < TK; j++) {
            float p = prow[j];
            float4 vv = *(float4*)&sV[j * HD + d4];
            oacc.x += p * vv.x; oacc.y += p * vv.y;
            oacc.z += p * vv.z; oacc.w += p * vv.w;
        }
    }
    int sg = qt * TQ + qi;
    *(float4*)&g_ao[((size_t)b * S_ + sg) * DH + h * HD + d4] = oacc;
}

// ============================================================================
// LayerNorm over last dim (512), one block (128 thr) per row.
// ============================================================================
__global__ __launch_bounds__(128) void ln_kernel(
    const float* __restrict__ gamma, const float* __restrict__ beta,
    float* __restrict__ out)
{
    __shared__ float red[8];
    const int r = blockIdx.x;
    const int tid = threadIdx.x;
    float4 v = *(const float4*)&g_o[(size_t)r * 512 + tid * 4];
    float s  = v.x + v.y + v.z + v.w;
    float sq = v.x*v.x + v.y*v.y + v.z*v.z + v.w*v.w;
    #pragma unroll
    for (int o = 16; o > 0; o >>= 1) {
        s  += __shfl_xor_sync(~0u, s,  o);
        sq += __shfl_xor_sync(~0u, sq, o);
    }
    if ((tid & 31) == 0) { red[tid >> 5] = s; red[4 + (tid >> 5)] = sq; }
    __syncthreads();
    if (tid < 32) {
        float a  = (tid < 4) ? red[tid]     : 0.f;
        float b2 = (tid < 4) ? red[4 + tid] : 0.f;
        #pragma unroll
        for (int o = 2; o > 0; o >>= 1) {
            a  += __shfl_xor_sync(~0u, a,  o);
            b2 += __shfl_xor_sync(~0u, b2, o);
        }
        if (tid == 0) { red[0] = a; red[1] = b2; }
    }
    __syncthreads();
    float mean = red[0] * (1.f / 512.f);
    float var  = red[1] * (1.f / 512.f) - mean * mean;
    float inv  = rsqrtf(var + 1e-5f);
    int c = tid * 4;
    float4 g4 = *(const float4*)&gamma[c];
    float4 b4 = *(const float4*)&beta[c];
    float4 o4;
    o4.x = (v.x - mean) * inv * g4.x + b4.x;
    o4.y = (v.y - mean) * inv * g4.y + b4.y;
    o4.z = (v.z - mean) * inv * g4.z + b4.z;
    o4.w = (v.w - mean) * inv * g4.w + b4.w;
    *(float4*)&out[(size_t)r * 512 + c] = o4;
}

// ============================================================================
extern "C" void kernel_launch(void* const* d_in, const int* in_sizes, int n_in,
                              void* d_out, int out_size)
{
    const float* x    = (const float*)d_in[0];
    const int*   mask = (const int*)  d_in[1];
    const float* Wq   = (const float*)d_in[2];
    const float* bq   = (const float*)d_in[3];
    const float* Wk   = (const float*)d_in[4];
    const float* bk   = (const float*)d_in[5];
    const float* Wv   = (const float*)d_in[6];
    const float* bv   = (const float*)d_in[7];
    const float* pe   = (const float*)d_in[8];
    const float* Wo   = (const float*)d_in[9];
    const float* bo   = (const float*)d_in[10];
    const float* gam  = (const float*)d_in[11];
    const float* bet  = (const float*)d_in[12];
    float* out = (float*)d_out;

    float *qp, *kp, *vp, *aop, *op;
    cudaGetSymbolAddress((void**)&qp,  g_q);
    cudaGetSymbolAddress((void**)&kp,  g_k);
    cudaGetSymbolAddress((void**)&vp,  g_v);
    cudaGetSymbolAddress((void**)&aop, g_ao);
    cudaGetSymbolAddress((void**)&op,  g_o);

    const size_t out_elems  = (size_t)M_ * DH;                     // 4194304
    const size_t attn_elems = (size_t)B_ * H_ * S_ * S_;           // 134217728
    int write_attn = ((size_t)out_size >= out_elems + attn_elems) ? 1 : 0;
    float* attn_ptr = out + out_elems;

    const int ATTN_SMEM = (TQ*HD + 64*KTS + TQ*S_) * 4;            // 168960 B
    cudaFuncSetAttribute(attn_kernel,
                         cudaFuncAttributeMaxDynamicSharedMemorySize, ATTN_SMEM);

    dim3 gg(8, 128);
    gemm64<<<gg, 256>>>(x, Wq, bq, pe,      qp, 1);
    gemm64<<<gg, 256>>>(x, Wk, bk, pe,      kp, 1);
    gemm64<<<gg, 256>>>(x, Wv, bv, nullptr, vp, 1);

    attn_kernel<<<dim3(S_/TQ, H_, B_), 256, ATTN_SMEM>>>(mask, attn_ptr, write_attn);

    gemm64<<<gg, 256>>>(aop, Wo, bo, nullptr, op, 0);
    ln_kernel<<<M_, 128>>>(gam, bet, out);
}

// round 3
// speedup vs baseline: 2.6999x; 2.6999x over previous
#include <cuda_runtime.h>
#include <math.h>
#include <float.h>

#define B_   4
#define S_   2048
#define DIN  512
#define DH   512
#define H_   8
#define HD   64
#define M_   (B_*S_)          // 8192 rows

// -------- scratch (device globals; no allocations allowed) --------
__device__ float g_q [B_*H_*S_*HD];   // [B,H,S,HD]
__device__ float g_k [B_*H_*S_*HD];
__device__ float g_v [B_*H_*S_*HD];
__device__ float g_ao[M_*DH];         // attention output, [B,S,DH]
__device__ float g_o [M_*DH];         // after Wo, pre-LN
__device__ float g_attn_fb[(size_t)B_*H_*S_*S_];  // fallback score buffer

// ============================================================================
// GEMM: C[M,512] = X[M,512] @ W[512,512] (+bias) (+pos_enc)
// BM=128, BN=64, BK=32, 256 threads, 8x4 micro-tile.
// ============================================================================
__global__ __launch_bounds__(256) void gemm128(
    const float* __restrict__ X, const float* __restrict__ W,
    const float* __restrict__ bias, const float* __restrict__ pe,
    float* __restrict__ out, int scatter)
{
    __shared__ float As[32][132];   // A^T tile: As[k][m]
    __shared__ float Bs[32][64];
    const int tid = threadIdx.x;
    const int tx = tid & 15, ty = tid >> 4;
    const int rowBase = blockIdx.y * 128;
    const int colBase = blockIdx.x * 64;

    float acc[8][4] = {};
    for (int k0 = 0; k0 < 512; k0 += 32) {
        #pragma unroll
        for (int i = 0; i < 4; i++) {
            int r = (tid >> 3) + i * 32;
            int c = (tid & 7) * 4;
            float4 a = *(const float4*)&X[(size_t)(rowBase + r) * 512 + k0 + c];
            As[c  ][r] = a.x; As[c+1][r] = a.y; As[c+2][r] = a.z; As[c+3][r] = a.w;
        }
        #pragma unroll
        for (int i = 0; i < 2; i++) {
            int r = (tid >> 4) + i * 16;
            int c = (tid & 15) * 4;
            *(float4*)&Bs[r][c] = *(const float4*)&W[(size_t)(k0 + r) * 512 + colBase + c];
        }
        __syncthreads();
        #pragma unroll
        for (int kk = 0; kk < 32; kk++) {
            float4 a0 = *(float4*)&As[kk][ty*8];
            float4 a1 = *(float4*)&As[kk][ty*8 + 4];
            float4 b4 = *(float4*)&Bs[kk][tx*4];
            float a[8] = {a0.x,a0.y,a0.z,a0.w,a1.x,a1.y,a1.z,a1.w};
            float b[4] = {b4.x,b4.y,b4.z,b4.w};
            #pragma unroll
            for (int i = 0; i < 8; i++)
                #pragma unroll
                for (int j = 0; j < 4; j++)
                    acc[i][j] += a[i] * b[j];
        }
        __syncthreads();
    }

    const int c = colBase + tx * 4;
    float4 bi = *(const float4*)&bias[c];
    const int h = c >> 6, d = c & 63;
    #pragma unroll
    for (int i = 0; i < 8; i++) {
        int r = rowBase + ty*8 + i;
        int bb = r >> 11;
        int s  = r & 2047;
        float4 v = {acc[i][0]+bi.x, acc[i][1]+bi.y, acc[i][2]+bi.z, acc[i][3]+bi.w};
        if (scatter) {
            if (pe) {
                float4 p = *(const float4*)&pe[(size_t)s * DH + c];
                v.x += p.x; v.y += p.y; v.z += p.z; v.w += p.w;
            }
            *(float4*)&out[(((size_t)bb * H_ + h) * S_ + s) * HD + d] = v;
        } else {
            *(float4*)&out[(size_t)r * 512 + c] = v;
        }
    }
}

// ============================================================================
// K1: scores[bh, m, n] = (Q[m,:] . K[n,:]) / 8, masked -> raw to attn buffer
// 64x64 output tile, K-dim = 64 (single pass), 4x4 micro-tile.
// ============================================================================
__global__ __launch_bounds__(256) void scores_kernel(
    const int* __restrict__ mask, float* __restrict__ attn)
{
    __shared__ float Qs[64][68];   // [d][m]
    __shared__ float Ks[64][68];   // [d][n]
    const int tid = threadIdx.x;
    const int tx = tid & 15, ty = tid >> 4;
    const int nBase = blockIdx.x * 64;
    const int mBase = blockIdx.y * 64;
    const int bh = blockIdx.z;
    const int b  = bh >> 3;

    const float* qp = g_q + ((size_t)bh * S_ + mBase) * HD;
    const float* kp = g_k + ((size_t)bh * S_ + nBase) * HD;

    #pragma unroll
    for (int i = 0; i < 4; i++) {
        int r = (tid >> 4) + i * 16;          // 0..63
        int cc = (tid & 15) * 4;              // 0..60
        float4 q = *(const float4*)&qp[(size_t)r * HD + cc];
        Qs[cc  ][r] = q.x; Qs[cc+1][r] = q.y; Qs[cc+2][r] = q.z; Qs[cc+3][r] = q.w;
        float4 k = *(const float4*)&kp[(size_t)r * HD + cc];
        Ks[cc  ][r] = k.x; Ks[cc+1][r] = k.y; Ks[cc+2][r] = k.z; Ks[cc+3][r] = k.w;
    }
    __syncthreads();

    float acc[4][4] = {};
    #pragma unroll
    for (int kk = 0; kk < 64; kk++) {
        float4 a4 = *(float4*)&Qs[kk][ty*4];
        float4 b4 = *(float4*)&Ks[kk][tx*4];
        float a[4] = {a4.x,a4.y,a4.z,a4.w};
        float b[4] = {b4.x,b4.y,b4.z,b4.w};
        #pragma unroll
        for (int i = 0; i < 4; i++)
            #pragma unroll
            for (int j = 0; j < 4; j++)
                acc[i][j] += a[i] * b[j];
    }

    const int nc = nBase + tx * 4;
    #pragma unroll
    for (int i = 0; i < 4; i++) {
        int qrow = mBase + ty*4 + i;
        int4 m4 = *(const int4*)&mask[((size_t)b * S_ + qrow) * S_ + nc];
        float4 v;
        v.x = m4.x ? acc[i][0]*0.125f : -FLT_MAX;
        v.y = m4.y ? acc[i][1]*0.125f : -FLT_MAX;
        v.z = m4.z ? acc[i][2]*0.125f : -FLT_MAX;
        v.w = m4.w ? acc[i][3]*0.125f : -FLT_MAX;
        *(float4*)&attn[((size_t)bh * S_ + qrow) * S_ + nc] = v;
    }
}

// ============================================================================
// K2: row softmax in place. One block (256 thr) per row of 2048.
// ============================================================================
__global__ __launch_bounds__(256) void softmax_kernel(float* __restrict__ attn)
{
    __shared__ float red[8];
    const int tid = threadIdx.x;
    float4* p = (float4*)(attn + (size_t)blockIdx.x * S_);
    float4 v0 = p[tid];
    float4 v1 = p[tid + 256];

    float mx = fmaxf(fmaxf(fmaxf(v0.x,v0.y), fmaxf(v0.z,v0.w)),
                     fmaxf(fmaxf(v1.x,v1.y), fmaxf(v1.z,v1.w)));
    #pragma unroll
    for (int o = 16; o > 0; o >>= 1) mx = fmaxf(mx, __shfl_xor_sync(~0u, mx, o));
    if ((tid & 31) == 0) red[tid >> 5] = mx;
    __syncthreads();
    mx = red[0];
    #pragma unroll
    for (int i = 1; i < 8; i++) mx = fmaxf(mx, red[i]);
    __syncthreads();

    v0.x = __expf(v0.x - mx); v0.y = __expf(v0.y - mx);
    v0.z = __expf(v0.z - mx); v0.w = __expf(v0.w - mx);
    v1.x = __expf(v1.x - mx); v1.y = __expf(v1.y - mx);
    v1.z = __expf(v1.z - mx); v1.w = __expf(v1.w - mx);
    float s = v0.x+v0.y+v0.z+v0.w + v1.x+v1.y+v1.z+v1.w;
    #pragma unroll
    for (int o = 16; o > 0; o >>= 1) s += __shfl_xor_sync(~0u, s, o);
    if ((tid & 31) == 0) red[tid >> 5] = s;
    __syncthreads();
    s = red[0];
    #pragma unroll
    for (int i = 1; i < 8; i++) s += red[i];
    float inv = 1.f / s;

    v0.x *= inv; v0.y *= inv; v0.z *= inv; v0.w *= inv;
    v1.x *= inv; v1.y *= inv; v1.z *= inv; v1.w *= inv;
    p[tid] = v0;
    p[tid + 256] = v1;
}

// ============================================================================
// K3: O[bh, m, :] = P[bh, m, :] @ V[bh, :, 64].  BM=64, BN=64, BK=32.
// ============================================================================
__global__ __launch_bounds__(256) void pv_kernel(
    const float* __restrict__ attn)
{
    __shared__ float Ps[32][68];   // P^T tile: [k][m]
    __shared__ float Vs[32][64];   // [k][n]
    const int tid = threadIdx.x;
    const int tx = tid & 15, ty = tid >> 4;
    const int mBase = blockIdx.x * 64;
    const int bh = blockIdx.y;
    const int b = bh >> 3, h = bh & 7;

    const float* prow = attn + ((size_t)bh * S_ + mBase) * S_;
    const float* vp   = g_v + (size_t)bh * S_ * HD;

    float acc[4][4] = {};
    for (int k0 = 0; k0 < S_; k0 += 32) {
        #pragma unroll
        for (int i = 0; i < 2; i++) {
            int r = (tid >> 3) + i * 32;       // 0..63
            int c = (tid & 7) * 4;             // 0..28
            float4 pv = *(const float4*)&prow[(size_t)r * S_ + k0 + c];
            Ps[c  ][r] = pv.x; Ps[c+1][r] = pv.y; Ps[c+2][r] = pv.z; Ps[c+3][r] = pv.w;
        }
        #pragma unroll
        for (int i = 0; i < 2; i++) {
            int r = (tid >> 4) + i * 16;       // 0..31
            int c = (tid & 15) * 4;
            *(float4*)&Vs[r][c] = *(const float4*)&vp[(size_t)(k0 + r) * HD + c];
        }
        __syncthreads();
        #pragma unroll
        for (int kk = 0; kk < 32; kk++) {
            float4 a4 = *(float4*)&Ps[kk][ty*4];
            float4 b4 = *(float4*)&Vs[kk][tx*4];
            float a[4] = {a4.x,a4.y,a4.z,a4.w};
            float b[4] = {b4.x,b4.y,b4.z,b4.w};
            #pragma unroll
            for (int i = 0; i < 4; i++)
                #pragma unroll
                for (int j = 0; j < 4; j++)
                    acc[i][j] += a[i] * b[j];
        }
        __syncthreads();
    }

    #pragma unroll
    for (int i = 0; i < 4; i++) {
        int s = mBase + ty*4 + i;
        float4 v = {acc[i][0], acc[i][1], acc[i][2], acc[i][3]};
        *(float4*)&g_ao[((size_t)b * S_ + s) * DH + h * HD + tx*4] = v;
    }
}

// ============================================================================
// LayerNorm over last dim (512), one block (128 thr) per row.
// ============================================================================
__global__ __launch_bounds__(128) void ln_kernel(
    const float* __restrict__ gamma, const float* __restrict__ beta,
    float* __restrict__ out)
{
    __shared__ float red[8];
    const int r = blockIdx.x;
    const int tid = threadIdx.x;
    float4 v = *(const float4*)&g_o[(size_t)r * 512 + tid * 4];
    float s  = v.x + v.y + v.z + v.w;
    float sq = v.x*v.x + v.y*v.y + v.z*v.z + v.w*v.w;
    #pragma unroll
    for (int o = 16; o > 0; o >>= 1) {
        s  += __shfl_xor_sync(~0u, s,  o);
        sq += __shfl_xor_sync(~0u, sq, o);
    }
    if ((tid & 31) == 0) { red[tid >> 5] = s; red[4 + (tid >> 5)] = sq; }
    __syncthreads();
    if (tid < 32) {
        float a  = (tid < 4) ? red[tid]     : 0.f;
        float b2 = (tid < 4) ? red[4 + tid] : 0.f;
        #pragma unroll
        for (int o = 2; o > 0; o >>= 1) {
            a  += __shfl_xor_sync(~0u, a,  o);
            b2 += __shfl_xor_sync(~0u, b2, o);
        }
        if (tid == 0) { red[0] = a; red[1] = b2; }
    }
    __syncthreads();
    float mean = red[0] * (1.f / 512.f);
    float var  = red[1] * (1.f / 512.f) - mean * mean;
    float inv  = rsqrtf(var + 1e-5f);
    int c = tid * 4;
    float4 g4 = *(const float4*)&gamma[c];
    float4 b4 = *(const float4*)&beta[c];
    float4 o4;
    o4.x = (v.x - mean) * inv * g4.x + b4.x;
    o4.y = (v.y - mean) * inv * g4.y + b4.y;
    o4.z = (v.z - mean) * inv * g4.z + b4.z;
    o4.w = (v.w - mean) * inv * g4.w + b4.w;
    *(float4*)&out[(size_t)r * 512 + c] = o4;
}

// ============================================================================
extern "C" void kernel_launch(void* const* d_in, const int* in_sizes, int n_in,
                              void* d_out, int out_size)
{
    const float* x    = (const float*)d_in[0];
    const int*   mask = (const int*)  d_in[1];
    const float* Wq   = (const float*)d_in[2];
    const float* bq   = (const float*)d_in[3];
    const float* Wk   = (const float*)d_in[4];
    const float* bk   = (const float*)d_in[5];
    const float* Wv   = (const float*)d_in[6];
    const float* bv   = (const float*)d_in[7];
    const float* pe   = (const float*)d_in[8];
    const float* Wo   = (const float*)d_in[9];
    const float* bo   = (const float*)d_in[10];
    const float* gam  = (const float*)d_in[11];
    const float* bet  = (const float*)d_in[12];
    float* out = (float*)d_out;

    float *qp, *kp, *vp, *aop, *op, *fb;
    cudaGetSymbolAddress((void**)&qp,  g_q);
    cudaGetSymbolAddress((void**)&kp,  g_k);
    cudaGetSymbolAddress((void**)&vp,  g_v);
    cudaGetSymbolAddress((void**)&aop, g_ao);
    cudaGetSymbolAddress((void**)&op,  g_o);
    cudaGetSymbolAddress((void**)&fb,  g_attn_fb);

    const size_t out_elems  = (size_t)M_ * DH;                     // 4194304
    const size_t attn_elems = (size_t)B_ * H_ * S_ * S_;           // 134217728
    int write_attn = ((size_t)out_size >= out_elems + attn_elems) ? 1 : 0;
    float* attn_buf = write_attn ? (out + out_elems) : fb;

    dim3 gg(8, 64);
    gemm128<<<gg, 256>>>(x, Wq, bq, pe,      qp, 1);
    gemm128<<<gg, 256>>>(x, Wk, bk, pe,      kp, 1);
    gemm128<<<gg, 256>>>(x, Wv, bv, nullptr, vp, 1);

    scores_kernel <<<dim3(32, 32, 32), 256>>>(mask, attn_buf);
    softmax_kernel<<<B_*H_*S_, 256>>>(attn_buf);
    pv_kernel     <<<dim3(32, 32), 256>>>(attn_buf);

    gemm128<<<gg, 256>>>(aop, Wo, bo, nullptr, op, 0);
    ln_kernel<<<M_, 128>>>(gam, bet, out);
}